// round 6
// baseline (speedup 1.0000x reference)
#include <cuda_runtime.h>
#include <math.h>

typedef unsigned long long u64;

// ---- packed f32x2 helpers (sm_103a; ptxas won't auto-fuse) ----
__device__ __forceinline__ u64 pack2(float x, float y) {
    u64 r; asm("mov.b64 %0, {%1, %2};" : "=l"(r) : "f"(x), "f"(y)); return r;
}
__device__ __forceinline__ u64 fma2(u64 a, u64 b, u64 c) {
    u64 d; asm("fma.rn.f32x2 %0, %1, %2, %3;" : "=l"(d) : "l"(a), "l"(b), "l"(c)); return d;
}
__device__ __forceinline__ u64 mul2(u64 a, u64 b) {
    u64 d; asm("mul.rn.f32x2 %0, %1, %2;" : "=l"(d) : "l"(a), "l"(b)); return d;
}
__device__ __forceinline__ u64 add2(u64 a, u64 b) {
    u64 d; asm("add.rn.f32x2 %0, %1, %2;" : "=l"(d) : "l"(a), "l"(b)); return d;
}
__device__ __forceinline__ float2 unpack2(u64 v) {
    float x, y; asm("mov.b64 {%0, %1}, %2;" : "=f"(x), "=f"(y) : "l"(v)); return make_float2(x, y);
}

#define MAXB 8192
#define TILE 128

// 4 fixed base matrices in the 9-dim trig basis, n padded to 10 (col 9 = 0):
// g_Nb[(w*9 + m)*10 + n],  u^T N_w v = qfeat_w for the patch.
__device__ float g_Nb[360];
// per-(row-group, image) partials: [0:14B) sum, [14B:28B) sumsq, [28B:42B) qdot
__device__ float g_part[3 * 14 * MAXB];

// L[(alpha*4+alpha')][m]: half-angle outer products -> 9-dim full-angle basis
// u = (1, c1, s1, c0, c0c1, c0s1, s0, s0c1, s0s1), factor 1/4 per side folded later.
__constant__ float L9[16][9] = {
    {1, 1, 0, 1, 1, 0, 0, 0, 0},   // (0,0)
    {0, 0, 1, 0, 0, 1, 0, 0, 0},   // (0,1)
    {0, 0, 0, 0, 0, 0, 1, 1, 0},   // (0,2)
    {0, 0, 0, 0, 0, 0, 0, 0, 1},   // (0,3)
    {0, 0, 1, 0, 0, 1, 0, 0, 0},   // (1,0)
    {1,-1, 0, 1,-1, 0, 0, 0, 0},   // (1,1)
    {0, 0, 0, 0, 0, 0, 0, 0, 1},   // (1,2)
    {0, 0, 0, 0, 0, 0, 1,-1, 0},   // (1,3)
    {0, 0, 0, 0, 0, 0, 1, 1, 0},   // (2,0)
    {0, 0, 0, 0, 0, 0, 0, 0, 1},   // (2,1)
    {1, 1, 0,-1,-1, 0, 0, 0, 0},   // (2,2)
    {0, 0, 1, 0, 0,-1, 0, 0, 0},   // (2,3)
    {0, 0, 0, 0, 0, 0, 0, 0, 1},   // (3,0)
    {0, 0, 0, 0, 0, 0, 1,-1, 0},   // (3,1)
    {0, 0, 1, 0, 0,-1, 0, 0, 0},   // (3,2)
    {1,-1, 0,-1, 1, 0, 0, 0, 0}    // (3,3)
};

// ---------------------------------------------------------------------------
// Kernel 1 (single block): build H_w = sum_k Z[k,w] Re(u_k u_k^H) (16x16),
// then collapse through the psi = a01 (x) a23 tensor structure to the four
// 9x9 base matrices N_w in the full-angle trig basis (x 1/16).
// ---------------------------------------------------------------------------
__global__ void __launch_bounds__(256) precomp_base(const float* __restrict__ U_re,
                                                    const float* __restrict__ U_im)
{
    __shared__ float urs[256], uis[256];
    __shared__ float Hsh[4][256];
    __shared__ float T1[4][9][16];
    const int t = threadIdx.x;
    for (int i = t; i < 256; i += 256) { urs[i] = U_re[i]; uis[i] = U_im[i]; }
    __syncthreads();

    // H_w[r][c], full 16x16 per w
    for (int e = t; e < 1024; e += 256) {
        const int w = e >> 8, rc = e & 255, r = rc >> 4, c = rc & 15;
        float acc = 0.f;
        #pragma unroll
        for (int k = 0; k < 16; k++) {
            float z = ((k >> (3 - w)) & 1) ? -1.f : 1.f;
            acc += z * (urs[k * 16 + r] * urs[k * 16 + c] +
                        uis[k * 16 + r] * uis[k * 16 + c]);
        }
        Hsh[w][rc] = acc;
    }
    __syncthreads();

    // contract (alpha, alpha') -> m:  T1[w][m][4*b1+b2]
    for (int e = t; e < 576; e += 256) {
        const int w = e / 144, rem = e % 144, m = rem / 16, bb = rem % 16;
        const int b1 = bb >> 2, b2 = bb & 3;
        float acc = 0.f;
        #pragma unroll
        for (int aa = 0; aa < 16; aa++) {
            float coef = L9[aa][m];
            if (coef != 0.f) {
                const int a1 = aa >> 2, a2 = aa & 3;
                acc += coef * Hsh[w][(4 * a1 + b1) * 16 + 4 * a2 + b2];
            }
        }
        T1[w][m][bb] = acc;
    }
    __syncthreads();

    // contract (beta, beta') -> n; scale 1/16; pad n=9 with zeros
    for (int e = t; e < 360; e += 256) {
        const int w = e / 90, rem = e % 90, m = rem / 10, n = rem % 10;
        float acc = 0.f;
        if (n < 9) {
            #pragma unroll
            for (int bb = 0; bb < 16; bb++) {
                float coef = L9[bb][n];
                if (coef != 0.f) acc += coef * T1[w][m][bb];
            }
            acc *= 0.0625f;
        }
        g_Nb[e] = acc;
    }
}

// ---------------------------------------------------------------------------
// Kernel 2: quantum branch. Block = 128 images x one patch-row group.
// Prologue folds wc into 14 per-patch 9x9 matrices (4-term lin. combo of
// the bases). Main loop: 9x9 bilinear form per patch with v-pairs packed
// into f32x2 lanes. Deterministic partial writes, no atomics.
// ---------------------------------------------------------------------------
__global__ void __launch_bounds__(TILE) quantum_kernel(const float* __restrict__ x,
                                                       const float* __restrict__ w_cls,
                                                       int B)
{
    __shared__ float xs[TILE * 57];                 // 57-pad: conflict-free rows
    __shared__ __align__(16) u64 Ms[14 * 54];       // 14 folded matrices (6 KB)
    __shared__ float Nb[360];
    __shared__ float wcs[56];

    const int t  = threadIdx.x;
    const int b0 = blockIdx.x * TILE;
    const int rg = blockIdx.y;                      // 0..13

    for (int i = t; i < 360; i += TILE) Nb[i] = g_Nb[i];
    if (t < 56) wcs[t] = w_cls[1 + 56 * rg + t];

    const int nimg = min(TILE, B - b0);
    const float* xb = x + (size_t)b0 * 784 + rg * 56;   // rows 2rg,2rg+1 contiguous
    for (int i = t; i < nimg * 56; i += TILE) {
        int img = i / 56, c = i - img * 56;
        xs[img * 57 + c] = xb[(size_t)img * 784 + c];
    }
    __syncthreads();

    // fold: Ms[pc*54 + m*6 + np] = ( N_p[m][2np], N_p[m][2np+1] )
    for (int e = t; e < 14 * 45; e += TILE) {
        const int pc = e / 45, r = e % 45, m = r / 5, np = r % 5;
        float lo = 0.f, hi = 0.f;
        #pragma unroll
        for (int w = 0; w < 4; w++) {
            float wc = wcs[pc * 4 + w];
            lo += wc * Nb[(w * 9 + m) * 10 + 2 * np];
            hi += wc * Nb[(w * 9 + m) * 10 + 2 * np + 1];
        }
        Ms[pc * 54 + m * 6 + np] = pack2(lo, hi);
    }
    __syncthreads();
    if (t >= nimg) return;                          // no further block syncs

    u64 s2 = 0ull, sq2 = 0ull;                      // packed mean/sumsq partials
    float C = 0.f;
    const float* xt = xs + t * 57;

    #pragma unroll 1
    for (int pc = 0; pc < 14; pc++) {
        const float p0 = xt[2 * pc], p1 = xt[2 * pc + 1];
        const float p2 = xt[28 + 2 * pc], p3 = xt[29 + 2 * pc];
        const u64 x01 = pack2(p0, p1), x23 = pack2(p2, p3);
        s2  = add2(s2, add2(x01, x23));
        sq2 = fma2(x01, x01, fma2(x23, x23, sq2));

        float sn0, cs0, sn1, cs1, sn2, cs2, sn3, cs3;
        __sincosf(p0, &sn0, &cs0);
        __sincosf(p1, &sn1, &cs1);
        __sincosf(p2, &sn2, &cs2);
        __sincosf(p3, &sn3, &cs3);

        // u = (1, c1, s1, c0, c0c1, c0s1, s0, s0c1, s0s1), v likewise on p2,p3
        const float u4 = cs0 * cs1, u5 = cs0 * sn1, u7 = sn0 * cs1, u8 = sn0 * sn1;
        const float v4 = cs2 * cs3, v5 = cs2 * sn3, v7 = sn2 * cs3, v8 = sn2 * sn3;
        const u64 vp0 = pack2(1.f, cs3), vp1 = pack2(sn3, cs2);
        const u64 vp2 = pack2(v4, v5),   vp3 = pack2(sn2, v7);
        const u64 vp4 = pack2(v8, 0.f);
        const float us[9] = {1.f, cs1, sn1, cs0, u4, u5, sn0, u7, u8};

        const u64* Mp = Ms + pc * 54;
        u64 c2a = 0ull, c2b = 0ull;
        #pragma unroll
        for (int m = 0; m < 9; m++) {
            const ulonglong2* row = (const ulonglong2*)(Mp + m * 6);
            const ulonglong2 e01 = row[0];             // np 0,1  (broadcast LDS.128)
            const ulonglong2 e23 = row[1];             // np 2,3
            u64 y = mul2(e01.x, vp0);
            y = fma2(e01.y, vp1, y);
            y = fma2(e23.x, vp2, y);
            y = fma2(e23.y, vp3, y);
            y = fma2(Mp[m * 6 + 4], vp4, y);           // np 4 (v8, 0)
            const u64 uu = pack2(us[m], us[m]);
            if (m & 1) c2b = fma2(y, uu, c2b);
            else       c2a = fma2(y, uu, c2a);
        }
        const float2 cc = unpack2(add2(c2a, c2b));
        C += cc.x + cc.y;
    }

    const float2 sv = unpack2(s2);
    const float2 qv = unpack2(sq2);
    const int b = b0 + t;
    g_part[rg * B + b]        = sv.x + sv.y;
    g_part[(14 + rg) * B + b] = qv.x + qv.y;
    g_part[(28 + rg) * B + b] = C;
}

// ---------------------------------------------------------------------------
// Kernel 3: sum partials, classical MLP, fuse, sigmoid.
// ---------------------------------------------------------------------------
__global__ void final_kernel(const float* __restrict__ w_in,  const float* __restrict__ b_in,
                             const float* __restrict__ scale_in, const float* __restrict__ shift_in,
                             const float* __restrict__ Wc,    const float* __restrict__ bc,
                             const float* __restrict__ scalec, const float* __restrict__ shiftc,
                             const float* __restrict__ w_out, const float* __restrict__ b_out,
                             const float* __restrict__ w_cls, const float* __restrict__ b_cls,
                             float* __restrict__ out, int B, int Lc)
{
    const int b = blockIdx.x * 256 + threadIdx.x;
    if (b >= B) return;
    float S = 0.f, Q = 0.f, C = 0.f;
    #pragma unroll
    for (int rg = 0; rg < 14; rg++) {
        S += g_part[rg * B + b];
        Q += g_part[(14 + rg) * B + b];
        C += g_part[(28 + rg) * B + b];
    }
    float mean = S * (1.f / 784.f);
    float var  = (Q - S * S * (1.f / 784.f)) * (1.f / 783.f);   // ddof=1
    float sd   = sqrtf(fmaxf(var, 0.f));
    float h0 = tanhf(mean * w_in[0] + sd * w_in[1] + b_in[0]) * scale_in[0] + shift_in[0];
    float h1 = tanhf(mean * w_in[2] + sd * w_in[3] + b_in[1]) * scale_in[1] + shift_in[1];
    for (int l = 0; l < Lc; l++) {
        float n0 = tanhf(h0 * Wc[l*4+0] + h1 * Wc[l*4+1] + bc[l*2+0]) * scalec[l*2+0] + shiftc[l*2+0];
        float n1 = tanhf(h0 * Wc[l*4+2] + h1 * Wc[l*4+3] + bc[l*2+1]) * scalec[l*2+1] + shiftc[l*2+1];
        h0 = n0; h1 = n1;
    }
    float cls   = h0 * w_out[0] + h1 * w_out[1] + b_out[0];
    float logit = b_cls[0] + cls * w_cls[0] + C;
    out[b] = 1.f / (1.f + __expf(-logit));
}

extern "C" void kernel_launch(void* const* d_in, const int* in_sizes, int n_in,
                              void* d_out, int out_size)
{
    const float* x        = (const float*)d_in[0];
    const float* w_in     = (const float*)d_in[1];
    const float* b_in     = (const float*)d_in[2];
    const float* scale_in = (const float*)d_in[3];
    const float* shift_in = (const float*)d_in[4];
    const float* Wc       = (const float*)d_in[5];
    const float* bc       = (const float*)d_in[6];
    const float* scalec   = (const float*)d_in[7];
    const float* shiftc   = (const float*)d_in[8];
    const float* w_out    = (const float*)d_in[9];
    const float* b_out    = (const float*)d_in[10];
    const float* U_re     = (const float*)d_in[11];
    const float* U_im     = (const float*)d_in[12];
    const float* w_cls    = (const float*)d_in[13];
    const float* b_cls    = (const float*)d_in[14];
    float* out = (float*)d_out;

    const int B  = in_sizes[0] / 784;   // (B,1,28,28)
    const int Lc = in_sizes[5] / 4;     // (L,2,2)

    precomp_base<<<1, 256>>>(U_re, U_im);

    dim3 grid((B + TILE - 1) / TILE, 14);
    quantum_kernel<<<grid, TILE>>>(x, w_cls, B);

    final_kernel<<<(B + 255) / 256, 256>>>(w_in, b_in, scale_in, shift_in,
                                           Wc, bc, scalec, shiftc, w_out, b_out,
                                           w_cls, b_cls, out, B, Lc);
}

// round 7
// speedup vs baseline: 1.1157x; 1.1157x over previous
#include <cuda_runtime.h>
#include <math.h>

typedef unsigned long long u64;

// ---- packed f32x2 helpers (sm_103a; ptxas won't auto-fuse) ----
__device__ __forceinline__ u64 pack2(float x, float y) {
    u64 r; asm("mov.b64 %0, {%1, %2};" : "=l"(r) : "f"(x), "f"(y)); return r;
}
__device__ __forceinline__ u64 fma2(u64 a, u64 b, u64 c) {
    u64 d; asm("fma.rn.f32x2 %0, %1, %2, %3;" : "=l"(d) : "l"(a), "l"(b), "l"(c)); return d;
}
__device__ __forceinline__ u64 mul2(u64 a, u64 b) {
    u64 d; asm("mul.rn.f32x2 %0, %1, %2;" : "=l"(d) : "l"(a), "l"(b)); return d;
}
__device__ __forceinline__ u64 add2(u64 a, u64 b) {
    u64 d; asm("add.rn.f32x2 %0, %1, %2;" : "=l"(d) : "l"(a), "l"(b)); return d;
}
__device__ __forceinline__ float2 unpack2(u64 v) {
    float x, y; asm("mov.b64 {%0, %1}, %2;" : "=f"(x), "=f"(y) : "l"(v)); return make_float2(x, y);
}

#define MAXB 8192
#define TILE 128

// per-(row-group, image) partials: [0:14B) sum, [14B:28B) sumsq, [28B:42B) qdot
__device__ float g_part[3 * 14 * MAXB];

// Sparse trig-basis contraction: column m of the half->full angle map has
// exactly 4 nonzeros at pair-indices CAA[m][q] with signs CSG[m][q].
__constant__ int   CAA[9][4] = {
    {0,5,10,15}, {0,5,10,15}, {1,4,11,14}, {0,5,10,15}, {0,5,10,15},
    {1,4,11,14}, {2,7,8,13}, {2,7,8,13}, {3,6,9,12}};
__constant__ float CSG[9][4] = {
    {1,1,1,1}, {1,-1,1,-1}, {1,1,1,1}, {1,1,-1,-1}, {1,-1,-1,1},
    {1,1,-1,-1}, {1,1,1,1}, {1,-1,1,-1}, {1,1,1,1}};

// triangular row base: base[r] = r*16 - r(r-1)/2
__constant__ int TRI_BASE[17] = {0,16,31,45,58,70,81,91,100,108,115,121,126,130,133,135,136};

// ---------------------------------------------------------------------------
// Quantum kernel (also recomputes the 4 base matrices per block — cheaper
// than a serial precomp launch). Block = 128 images x one patch-row group.
// Phased smem aliasing in `scratch`:
//   P1: urs[0..255], uis[256..511]
//   P2: Hs  = scratch+512   (4 x 256)
//   P3: T1  = scratch+1536  (4 x 144)
//   P4: Nbs = scratch+0     (360)     [urs/uis dead]
//   P5: Ms  = (u64*)(scratch+512), 756 u64   [Hs/T1 dead]
// ---------------------------------------------------------------------------
__global__ void __launch_bounds__(TILE) quantum_kernel(const float* __restrict__ x,
                                                       const float* __restrict__ U_re,
                                                       const float* __restrict__ U_im,
                                                       const float* __restrict__ w_cls,
                                                       int B)
{
    __shared__ float xs[TILE * 57];                 // 57-pad: conflict-free rows
    __shared__ __align__(16) float scratch[2112];   // 8448 B, phase-aliased

    const int t  = threadIdx.x;
    const int b0 = blockIdx.x * TILE;
    const int rg = blockIdx.y;                      // 0..13

    float* urs = scratch;
    float* uis = scratch + 256;
    float* Hs  = scratch + 512;      // [w*256 + r*16 + c]
    float* T1  = scratch + 1536;     // [w*144 + m*16 + bb]
    float* Nbs = scratch;            // [ (w*9+m)*10 + n ], n=9 padded 0
    u64*   Ms  = (u64*)(scratch + 512);  // [pc*54 + m*6 + np]

    // ---- image tile + U load ----
    const int nimg = min(TILE, B - b0);
    const float* xb = x + (size_t)b0 * 784 + rg * 56;  // rows 2rg,2rg+1 contiguous
    for (int i = t; i < nimg * 56; i += TILE) {
        int img = i / 56, c = i - img * 56;
        xs[img * 57 + c] = xb[(size_t)img * 784 + c];
    }
    for (int i = t; i < 256; i += TILE) { urs[i] = U_re[i]; uis[i] = U_im[i]; }
    __syncthreads();

    // ---- P2: H_w[r][c] = sum_k z_{k,w} (Ur[k,r]Ur[k,c] + Ui[k,r]Ui[k,c]),
    //      symmetric: 136 unique entries, signs fold at compile time ----
    for (int e = t; e < 136; e += TILE) {
        int r = 0;
        while (e >= TRI_BASE[r + 1]) r++;
        const int c = r + (e - TRI_BASE[r]);
        float h0 = 0.f, h1 = 0.f, h2 = 0.f, h3 = 0.f;
        #pragma unroll
        for (int k = 0; k < 16; k++) {
            float pr = urs[k * 16 + r] * urs[k * 16 + c]
                     + uis[k * 16 + r] * uis[k * 16 + c];
            h0 += (k & 8) ? -pr : pr;
            h1 += (k & 4) ? -pr : pr;
            h2 += (k & 2) ? -pr : pr;
            h3 += (k & 1) ? -pr : pr;
        }
        Hs[0 * 256 + r * 16 + c] = h0;  Hs[0 * 256 + c * 16 + r] = h0;
        Hs[1 * 256 + r * 16 + c] = h1;  Hs[1 * 256 + c * 16 + r] = h1;
        Hs[2 * 256 + r * 16 + c] = h2;  Hs[2 * 256 + c * 16 + r] = h2;
        Hs[3 * 256 + r * 16 + c] = h3;  Hs[3 * 256 + c * 16 + r] = h3;
    }
    __syncthreads();

    // ---- P3: contract (a1,a2) -> m (4 sparse terms each) ----
    for (int e = t; e < 576; e += TILE) {
        const int w = e / 144, rem = e % 144, m = rem >> 4, bb = rem & 15;
        const int b1 = bb >> 2, b2 = bb & 3;
        float acc = 0.f;
        #pragma unroll
        for (int q = 0; q < 4; q++) {
            const int aa = CAA[m][q], a1 = aa >> 2, a2 = aa & 3;
            acc = fmaf(CSG[m][q], Hs[w * 256 + (4 * a1 + b1) * 16 + 4 * a2 + b2], acc);
        }
        T1[w * 144 + m * 16 + bb] = acc;
    }
    __syncthreads();

    // ---- P4: contract (b1,b2) -> n, scale 1/16, pad n=9 with 0 ----
    for (int e = t; e < 360; e += TILE) {
        const int w = e / 90, rem = e % 90, m = rem / 10, n = rem % 10;
        float acc = 0.f;
        if (n < 9) {
            #pragma unroll
            for (int q = 0; q < 4; q++)
                acc = fmaf(CSG[n][q], T1[w * 144 + m * 16 + CAA[n][q]], acc);
            acc *= 0.0625f;
        }
        Nbs[e] = acc;
    }
    __syncthreads();

    // ---- P5: fold w_cls into 14 per-patch matrices ----
    for (int e = t; e < 14 * 45; e += TILE) {
        const int pc = e / 45, r = e % 45, m = r / 5, np = r % 5;
        const float* wc = w_cls + 1 + 4 * (rg * 14 + pc);
        float lo = 0.f, hi = 0.f;
        #pragma unroll
        for (int w = 0; w < 4; w++) {
            const float wcv = __ldg(wc + w);
            lo = fmaf(wcv, Nbs[(w * 9 + m) * 10 + 2 * np],     lo);
            hi = fmaf(wcv, Nbs[(w * 9 + m) * 10 + 2 * np + 1], hi);
        }
        Ms[pc * 54 + m * 6 + np] = pack2(lo, hi);
    }
    __syncthreads();
    if (t >= nimg) return;                          // no further block syncs

    // ---- main loop: 9x9 bilinear form per patch ----
    u64 s2 = 0ull, sq2 = 0ull;                      // packed mean/sumsq partials
    float C = 0.f;
    const float* xt = xs + t * 57;

    #pragma unroll 1
    for (int pc = 0; pc < 14; pc++) {
        const float p0 = xt[2 * pc], p1 = xt[2 * pc + 1];
        const float p2 = xt[28 + 2 * pc], p3 = xt[29 + 2 * pc];
        const u64 x01 = pack2(p0, p1), x23 = pack2(p2, p3);
        s2  = add2(s2, add2(x01, x23));
        sq2 = fma2(x01, x01, fma2(x23, x23, sq2));

        float sn0, cs0, sn1, cs1, sn2, cs2, sn3, cs3;
        __sincosf(p0, &sn0, &cs0);
        __sincosf(p1, &sn1, &cs1);
        __sincosf(p2, &sn2, &cs2);
        __sincosf(p3, &sn3, &cs3);

        // u = (1, c1, s1, c0, c0c1, c0s1, s0, s0c1, s0s1), v likewise on p2,p3
        const float u4 = cs0 * cs1, u5 = cs0 * sn1, u7 = sn0 * cs1, u8 = sn0 * sn1;
        const float v4 = cs2 * cs3, v5 = cs2 * sn3, v7 = sn2 * cs3, v8 = sn2 * sn3;
        const u64 vp0 = pack2(1.f, cs3), vp1 = pack2(sn3, cs2);
        const u64 vp2 = pack2(v4, v5),   vp3 = pack2(sn2, v7);
        const u64 vp4 = pack2(v8, 0.f);
        const float us[9] = {1.f, cs1, sn1, cs0, u4, u5, sn0, u7, u8};

        const u64* Mp = Ms + pc * 54;
        u64 c2a = 0ull, c2b = 0ull;
        #pragma unroll
        for (int m = 0; m < 9; m++) {
            const ulonglong2* row = (const ulonglong2*)(Mp + m * 6);
            const ulonglong2 e01 = row[0];             // np 0,1 (broadcast LDS.128)
            const ulonglong2 e23 = row[1];             // np 2,3
            u64 y = mul2(e01.x, vp0);
            y = fma2(e01.y, vp1, y);
            y = fma2(e23.x, vp2, y);
            y = fma2(e23.y, vp3, y);
            y = fma2(Mp[m * 6 + 4], vp4, y);           // np 4 (v8, 0)
            const u64 uu = pack2(us[m], us[m]);
            if (m & 1) c2b = fma2(y, uu, c2b);
            else       c2a = fma2(y, uu, c2a);
        }
        const float2 cc = unpack2(add2(c2a, c2b));
        C += cc.x + cc.y;
    }

    const float2 sv = unpack2(s2);
    const float2 qv = unpack2(sq2);
    const int b = b0 + t;
    g_part[rg * B + b]        = sv.x + sv.y;
    g_part[(14 + rg) * B + b] = qv.x + qv.y;
    g_part[(28 + rg) * B + b] = C;
}

// ---------------------------------------------------------------------------
// Final kernel: sum partials, classical MLP, fuse, sigmoid.
// ---------------------------------------------------------------------------
__global__ void final_kernel(const float* __restrict__ w_in,  const float* __restrict__ b_in,
                             const float* __restrict__ scale_in, const float* __restrict__ shift_in,
                             const float* __restrict__ Wc,    const float* __restrict__ bc,
                             const float* __restrict__ scalec, const float* __restrict__ shiftc,
                             const float* __restrict__ w_out, const float* __restrict__ b_out,
                             const float* __restrict__ w_cls, const float* __restrict__ b_cls,
                             float* __restrict__ out, int B, int Lc)
{
    const int b = blockIdx.x * 256 + threadIdx.x;
    if (b >= B) return;
    float S = 0.f, Q = 0.f, C = 0.f;
    #pragma unroll
    for (int rg = 0; rg < 14; rg++) {
        S += g_part[rg * B + b];
        Q += g_part[(14 + rg) * B + b];
        C += g_part[(28 + rg) * B + b];
    }
    float mean = S * (1.f / 784.f);
    float var  = (Q - S * S * (1.f / 784.f)) * (1.f / 783.f);   // ddof=1
    float sd   = sqrtf(fmaxf(var, 0.f));
    float h0 = tanhf(mean * w_in[0] + sd * w_in[1] + b_in[0]) * scale_in[0] + shift_in[0];
    float h1 = tanhf(mean * w_in[2] + sd * w_in[3] + b_in[1]) * scale_in[1] + shift_in[1];
    for (int l = 0; l < Lc; l++) {
        float n0 = tanhf(h0 * Wc[l*4+0] + h1 * Wc[l*4+1] + bc[l*2+0]) * scalec[l*2+0] + shiftc[l*2+0];
        float n1 = tanhf(h0 * Wc[l*4+2] + h1 * Wc[l*4+3] + bc[l*2+1]) * scalec[l*2+1] + shiftc[l*2+1];
        h0 = n0; h1 = n1;
    }
    float cls   = h0 * w_out[0] + h1 * w_out[1] + b_out[0];
    float logit = b_cls[0] + cls * w_cls[0] + C;
    out[b] = 1.f / (1.f + __expf(-logit));
}

extern "C" void kernel_launch(void* const* d_in, const int* in_sizes, int n_in,
                              void* d_out, int out_size)
{
    const float* x        = (const float*)d_in[0];
    const float* w_in     = (const float*)d_in[1];
    const float* b_in     = (const float*)d_in[2];
    const float* scale_in = (const float*)d_in[3];
    const float* shift_in = (const float*)d_in[4];
    const float* Wc       = (const float*)d_in[5];
    const float* bc       = (const float*)d_in[6];
    const float* scalec   = (const float*)d_in[7];
    const float* shiftc   = (const float*)d_in[8];
    const float* w_out    = (const float*)d_in[9];
    const float* b_out    = (const float*)d_in[10];
    const float* U_re     = (const float*)d_in[11];
    const float* U_im     = (const float*)d_in[12];
    const float* w_cls    = (const float*)d_in[13];
    const float* b_cls    = (const float*)d_in[14];
    float* out = (float*)d_out;

    const int B  = in_sizes[0] / 784;   // (B,1,28,28)
    const int Lc = in_sizes[5] / 4;     // (L,2,2)

    dim3 grid((B + TILE - 1) / TILE, 14);
    quantum_kernel<<<grid, TILE>>>(x, U_re, U_im, w_cls, B);

    final_kernel<<<(B + 255) / 256, 256>>>(w_in, b_in, scale_in, shift_in,
                                           Wc, bc, scalec, shiftc, w_out, b_out,
                                           w_cls, b_cls, out, B, Lc);
}

// round 8
// speedup vs baseline: 1.2038x; 1.0790x over previous
#include <cuda_runtime.h>
#include <math.h>

typedef unsigned long long u64;

// ---- packed f32x2 helpers (sm_103a; ptxas won't auto-fuse) ----
__device__ __forceinline__ u64 pack2(float x, float y) {
    u64 r; asm("mov.b64 %0, {%1, %2};" : "=l"(r) : "f"(x), "f"(y)); return r;
}
__device__ __forceinline__ u64 fma2(u64 a, u64 b, u64 c) {
    u64 d; asm("fma.rn.f32x2 %0, %1, %2, %3;" : "=l"(d) : "l"(a), "l"(b), "l"(c)); return d;
}
__device__ __forceinline__ u64 mul2(u64 a, u64 b) {
    u64 d; asm("mul.rn.f32x2 %0, %1, %2;" : "=l"(d) : "l"(a), "l"(b)); return d;
}
__device__ __forceinline__ u64 add2(u64 a, u64 b) {
    u64 d; asm("add.rn.f32x2 %0, %1, %2;" : "=l"(d) : "l"(a), "l"(b)); return d;
}
__device__ __forceinline__ float2 unpack2(u64 v) {
    float x, y; asm("mov.b64 {%0, %1}, %2;" : "=f"(x), "=f"(y) : "l"(v)); return make_float2(x, y);
}

#define MAXB 8192
#define TILE 128

// per-(row-group, image) partials: [0:14B) sum, [14B:28B) sumsq, [28B:42B) qdot
__device__ float g_part[3 * 14 * MAXB];
// per-image-tile completion counters (finisher resets to 0 -> replay-safe)
__device__ int g_cnt[(MAXB + TILE - 1) / TILE];

// Sparse trig-basis contraction: column m of the half->full angle map has
// exactly 4 nonzeros at pair-indices CAA[m][q] with signs CSG[m][q].
__constant__ int   CAA[9][4] = {
    {0,5,10,15}, {0,5,10,15}, {1,4,11,14}, {0,5,10,15}, {0,5,10,15},
    {1,4,11,14}, {2,7,8,13}, {2,7,8,13}, {3,6,9,12}};
__constant__ float CSG[9][4] = {
    {1,1,1,1}, {1,-1,1,-1}, {1,1,1,1}, {1,1,-1,-1}, {1,-1,-1,1},
    {1,1,-1,-1}, {1,1,1,1}, {1,-1,1,-1}, {1,1,1,1}};

// triangular row base: base[r] = r*16 - r(r-1)/2
__constant__ int TRI_BASE[17] = {0,16,31,45,58,70,81,91,100,108,115,121,126,130,133,135,136};

// ---------------------------------------------------------------------------
// Single fused kernel. Block = 128 images x one patch-row group.
// Prologue rebuilds the 4 base matrices from U (phased smem aliasing),
// folds w_cls into 14 per-patch 9x9 bilinear forms; main loop evaluates
// them; epilogue writes partials, and the LAST block per image tile
// (atomic counter) runs the classical MLP + sigmoid and writes out.
// ---------------------------------------------------------------------------
__global__ void __launch_bounds__(TILE) fused_kernel(
    const float* __restrict__ x,
    const float* __restrict__ U_re, const float* __restrict__ U_im,
    const float* __restrict__ w_cls,
    const float* __restrict__ w_in,  const float* __restrict__ b_in,
    const float* __restrict__ scale_in, const float* __restrict__ shift_in,
    const float* __restrict__ Wc,    const float* __restrict__ bc,
    const float* __restrict__ scalec, const float* __restrict__ shiftc,
    const float* __restrict__ w_out, const float* __restrict__ b_out,
    const float* __restrict__ b_cls,
    float* __restrict__ out, int B, int Lc)
{
    __shared__ float xs[TILE * 57];                 // 57-pad: conflict-free rows
    __shared__ __align__(16) float scratch[2112];   // 8448 B, phase-aliased
    __shared__ int s_old;

    const int t  = threadIdx.x;
    const int bx = blockIdx.x;
    const int b0 = bx * TILE;
    const int rg = blockIdx.y;                      // 0..13

    float* urs = scratch;
    float* uis = scratch + 256;
    float* Hs  = scratch + 512;      // [w*256 + r*16 + c]
    float* T1  = scratch + 1536;     // [w*144 + m*16 + bb]
    float* Nbs = scratch;            // [ (w*9+m)*10 + n ], n=9 padded 0
    u64*   Ms  = (u64*)(scratch + 512);  // [pc*54 + m*6 + np]

    // ---- image tile + U load ----
    const int nimg = min(TILE, B - b0);
    const float* xb = x + (size_t)b0 * 784 + rg * 56;  // rows 2rg,2rg+1 contiguous
    for (int i = t; i < nimg * 56; i += TILE) {
        int img = i / 56, c = i - img * 56;
        xs[img * 57 + c] = xb[(size_t)img * 784 + c];
    }
    for (int i = t; i < 256; i += TILE) { urs[i] = U_re[i]; uis[i] = U_im[i]; }
    __syncthreads();

    // ---- P2: H_w[r][c] (symmetric, 136 unique entries, Walsh signs) ----
    for (int e = t; e < 136; e += TILE) {
        int r = 0;
        while (e >= TRI_BASE[r + 1]) r++;
        const int c = r + (e - TRI_BASE[r]);
        float h0 = 0.f, h1 = 0.f, h2 = 0.f, h3 = 0.f;
        #pragma unroll
        for (int k = 0; k < 16; k++) {
            float pr = urs[k * 16 + r] * urs[k * 16 + c]
                     + uis[k * 16 + r] * uis[k * 16 + c];
            h0 += (k & 8) ? -pr : pr;
            h1 += (k & 4) ? -pr : pr;
            h2 += (k & 2) ? -pr : pr;
            h3 += (k & 1) ? -pr : pr;
        }
        Hs[0 * 256 + r * 16 + c] = h0;  Hs[0 * 256 + c * 16 + r] = h0;
        Hs[1 * 256 + r * 16 + c] = h1;  Hs[1 * 256 + c * 16 + r] = h1;
        Hs[2 * 256 + r * 16 + c] = h2;  Hs[2 * 256 + c * 16 + r] = h2;
        Hs[3 * 256 + r * 16 + c] = h3;  Hs[3 * 256 + c * 16 + r] = h3;
    }
    __syncthreads();

    // ---- P3: contract (a1,a2) -> m (4 sparse terms each) ----
    for (int e = t; e < 576; e += TILE) {
        const int w = e / 144, rem = e % 144, m = rem >> 4, bb = rem & 15;
        const int b1 = bb >> 2, b2 = bb & 3;
        float acc = 0.f;
        #pragma unroll
        for (int q = 0; q < 4; q++) {
            const int aa = CAA[m][q], a1 = aa >> 2, a2 = aa & 3;
            acc = fmaf(CSG[m][q], Hs[w * 256 + (4 * a1 + b1) * 16 + 4 * a2 + b2], acc);
        }
        T1[w * 144 + m * 16 + bb] = acc;
    }
    __syncthreads();

    // ---- P4: contract (b1,b2) -> n, scale 1/16, pad n=9 with 0 ----
    for (int e = t; e < 360; e += TILE) {
        const int w = e / 90, rem = e % 90, m = rem / 10, n = rem % 10;
        float acc = 0.f;
        if (n < 9) {
            #pragma unroll
            for (int q = 0; q < 4; q++)
                acc = fmaf(CSG[n][q], T1[w * 144 + m * 16 + CAA[n][q]], acc);
            acc *= 0.0625f;
        }
        Nbs[e] = acc;
    }
    __syncthreads();

    // ---- P5: fold w_cls into 14 per-patch matrices ----
    for (int e = t; e < 14 * 45; e += TILE) {
        const int pc = e / 45, r = e % 45, m = r / 5, np = r % 5;
        const float* wc = w_cls + 1 + 4 * (rg * 14 + pc);
        float lo = 0.f, hi = 0.f;
        #pragma unroll
        for (int w = 0; w < 4; w++) {
            const float wcv = __ldg(wc + w);
            lo = fmaf(wcv, Nbs[(w * 9 + m) * 10 + 2 * np],     lo);
            hi = fmaf(wcv, Nbs[(w * 9 + m) * 10 + 2 * np + 1], hi);
        }
        Ms[pc * 54 + m * 6 + np] = pack2(lo, hi);
    }
    __syncthreads();

    // ---- main loop: 9x9 bilinear form per patch (predicated, no return) ----
    if (t < nimg) {
        u64 s2 = 0ull, sq2 = 0ull;                  // packed mean/sumsq partials
        float C = 0.f;
        const float* xt = xs + t * 57;

        #pragma unroll 1
        for (int pc = 0; pc < 14; pc++) {
            const float p0 = xt[2 * pc], p1 = xt[2 * pc + 1];
            const float p2 = xt[28 + 2 * pc], p3 = xt[29 + 2 * pc];
            const u64 x01 = pack2(p0, p1), x23 = pack2(p2, p3);
            s2  = add2(s2, add2(x01, x23));
            sq2 = fma2(x01, x01, fma2(x23, x23, sq2));

            float sn0, cs0, sn1, cs1, sn2, cs2, sn3, cs3;
            __sincosf(p0, &sn0, &cs0);
            __sincosf(p1, &sn1, &cs1);
            __sincosf(p2, &sn2, &cs2);
            __sincosf(p3, &sn3, &cs3);

            // u = (1, c1, s1, c0, c0c1, c0s1, s0, s0c1, s0s1); v likewise on p2,p3
            const float u4 = cs0 * cs1, u5 = cs0 * sn1, u7 = sn0 * cs1, u8 = sn0 * sn1;
            const float v4 = cs2 * cs3, v5 = cs2 * sn3, v7 = sn2 * cs3, v8 = sn2 * sn3;
            const u64 vp0 = pack2(1.f, cs3), vp1 = pack2(sn3, cs2);
            const u64 vp2 = pack2(v4, v5),   vp3 = pack2(sn2, v7);
            const u64 vp4 = pack2(v8, 0.f);
            const float us[9] = {1.f, cs1, sn1, cs0, u4, u5, sn0, u7, u8};

            const u64* Mp = Ms + pc * 54;
            u64 c2a = 0ull, c2b = 0ull;
            #pragma unroll
            for (int m = 0; m < 9; m++) {
                const ulonglong2* row = (const ulonglong2*)(Mp + m * 6);
                const ulonglong2 e01 = row[0];         // np 0,1 (broadcast LDS.128)
                const ulonglong2 e23 = row[1];         // np 2,3
                u64 y = mul2(e01.x, vp0);
                y = fma2(e01.y, vp1, y);
                y = fma2(e23.x, vp2, y);
                y = fma2(e23.y, vp3, y);
                y = fma2(Mp[m * 6 + 4], vp4, y);       // np 4 (v8, 0)
                const u64 uu = pack2(us[m], us[m]);
                if (m & 1) c2b = fma2(y, uu, c2b);
                else       c2a = fma2(y, uu, c2a);
            }
            const float2 cc = unpack2(add2(c2a, c2b));
            C += cc.x + cc.y;
        }

        const float2 sv = unpack2(s2);
        const float2 qv = unpack2(sq2);
        const int b = b0 + t;
        g_part[rg * B + b]        = sv.x + sv.y;
        g_part[(14 + rg) * B + b] = qv.x + qv.y;
        g_part[(28 + rg) * B + b] = C;
    }

    // ---- last-block-done finisher ----
    __syncthreads();
    if (t == 0) {
        __threadfence();
        s_old = atomicAdd(&g_cnt[bx], 1);
    }
    __syncthreads();
    if (s_old != 13) return;

    if (t == 0) g_cnt[bx] = 0;        // reset for next launch / graph replay
    if (t >= nimg) return;

    const int b = b0 + t;
    float S = 0.f, Q = 0.f, C = 0.f;
    #pragma unroll
    for (int r = 0; r < 14; r++) {
        S += g_part[r * B + b];
        Q += g_part[(14 + r) * B + b];
        C += g_part[(28 + r) * B + b];
    }
    float mean = S * (1.f / 784.f);
    float var  = (Q - S * S * (1.f / 784.f)) * (1.f / 783.f);   // ddof=1
    float sd   = sqrtf(fmaxf(var, 0.f));
    float h0 = tanhf(mean * w_in[0] + sd * w_in[1] + b_in[0]) * scale_in[0] + shift_in[0];
    float h1 = tanhf(mean * w_in[2] + sd * w_in[3] + b_in[1]) * scale_in[1] + shift_in[1];
    for (int l = 0; l < Lc; l++) {
        float n0 = tanhf(h0 * Wc[l*4+0] + h1 * Wc[l*4+1] + bc[l*2+0]) * scalec[l*2+0] + shiftc[l*2+0];
        float n1 = tanhf(h0 * Wc[l*4+2] + h1 * Wc[l*4+3] + bc[l*2+1]) * scalec[l*2+1] + shiftc[l*2+1];
        h0 = n0; h1 = n1;
    }
    float cls   = h0 * w_out[0] + h1 * w_out[1] + b_out[0];
    float logit = b_cls[0] + cls * w_cls[0] + C;
    out[b] = 1.f / (1.f + __expf(-logit));
}

extern "C" void kernel_launch(void* const* d_in, const int* in_sizes, int n_in,
                              void* d_out, int out_size)
{
    const float* x        = (const float*)d_in[0];
    const float* w_in     = (const float*)d_in[1];
    const float* b_in     = (const float*)d_in[2];
    const float* scale_in = (const float*)d_in[3];
    const float* shift_in = (const float*)d_in[4];
    const float* Wc       = (const float*)d_in[5];
    const float* bc       = (const float*)d_in[6];
    const float* scalec   = (const float*)d_in[7];
    const float* shiftc   = (const float*)d_in[8];
    const float* w_out    = (const float*)d_in[9];
    const float* b_out    = (const float*)d_in[10];
    const float* U_re     = (const float*)d_in[11];
    const float* U_im     = (const float*)d_in[12];
    const float* w_cls    = (const float*)d_in[13];
    const float* b_cls    = (const float*)d_in[14];
    float* out = (float*)d_out;

    const int B  = in_sizes[0] / 784;   // (B,1,28,28)
    const int Lc = in_sizes[5] / 4;     // (L,2,2)

    dim3 grid((B + TILE - 1) / TILE, 14);
    fused_kernel<<<grid, TILE>>>(x, U_re, U_im, w_cls,
                                 w_in, b_in, scale_in, shift_in,
                                 Wc, bc, scalec, shiftc, w_out, b_out,
                                 b_cls, out, B, Lc);
}